// round 16
// baseline (speedup 1.0000x reference)
#include <cuda_runtime.h>

typedef unsigned long long ull;
typedef unsigned int u32;

#define NPOS   21824
#define NP4    (NPOS / 4)          // 5456
#define BATCH  8
#define KTOP   1000
#define NCLS   80
#define FULLM  0xffffffffu
#define NBINS  8192
#define HSHIFT 12
#define BASE_BIN 0x3D800u          // 0x3D800000 >> 12  (score 0.0625)
#define CAP    2048

// Scratch (no allocation allowed -> __device__ globals)
__device__ u32    g_score[BATCH * NPOS];
__device__ float4 g_boxes[BATCH * NPOS];
__device__ float  g_kind[BATCH * NPOS];
__device__ u32    g_hist[BATCH * NBINS];   // zero-init; consumed+re-zeroed by fused

__constant__ int   c_off[5]    = {0, 16384, 20480, 21504, 21760};
__constant__ int   c_logw[5]   = {7, 6, 5, 4, 3};
__constant__ float c_stride[5] = {8.f, 16.f, 32.f, 64.f, 128.f};

struct Ptrs { const float* cls[5]; const float* reg[5]; };

// swizzled bin index: bank = (low5 ^ owner-lane) -> conflict-free strided scans
__device__ __forceinline__ u32 BSWZ(u32 b) { return b ^ ((b >> 5) & 31u); }

// ---------------------------------------------------------------------------
// Kernel 1: decode -> (score bits, box, kind) + global score histogram
// ---------------------------------------------------------------------------
__global__ void decode_kernel(Ptrs p) {
    int gid = blockIdx.x * blockDim.x + threadIdx.x;
    if (gid >= BATCH * NPOS) return;
    int b   = gid / NPOS;
    int pos = gid - b * NPOS;

    int lev = 0;
    if      (pos >= c_off[4]) lev = 4;
    else if (pos >= c_off[3]) lev = 3;
    else if (pos >= c_off[2]) lev = 2;
    else if (pos >= c_off[1]) lev = 1;

    int local = pos - c_off[lev];
    int lw = c_logw[lev];
    int w  = 1 << lw;
    int hw = w * w;
    int y  = local >> lw;
    int x  = local & (w - 1);

    const float* __restrict__ cbase = p.cls[lev] + (size_t)b * NCLS * hw + local;
    float best = cbase[0];
    int   bi   = 0;
    #pragma unroll 16
    for (int c = 1; c < NCLS; c++) {
        float v = cbase[(size_t)c * hw];
        if (v > best) { best = v; bi = c; }
    }
    float score = (best > 0.05f) ? best : 0.0f;

    const float* __restrict__ rbase = p.reg[lev] + (size_t)b * 4 * hw + local;
    float s  = c_stride[lev];
    float r0 = rbase[0]      * s;
    float r1 = rbase[hw]     * s;
    float r2 = rbase[2 * hw] * s;
    float r3 = rbase[3 * hw] * s;
    float cx = ((float)x + 0.5f) * s;
    float cy = ((float)y + 0.5f) * s;

    g_boxes[gid] = make_float4(cx - r0, cy - r1, cx + r2, cy + r3);
    g_kind[gid]  = (float)bi;
    u32 sb = __float_as_uint(score);
    g_score[gid] = sb;

    int idx = (int)(sb >> HSHIFT) - (int)BASE_BIN;
    idx = idx < 0 ? 0 : (idx > NBINS - 1 ? NBINS - 1 : idx);
    atomicAdd(&g_hist[b * NBINS + idx], 1u);
}

// ---------------------------------------------------------------------------
// Kernel 2 (FUSED): per-image block.
//   hist suffix-scan -> binfloor -> collect scan (+ inline 32768-bin smem
//   key histogram) -> COUNTING-RANK sort (suffix scan of bins, slot scatter,
//   per-bin tie-fix by full key) -> class-bucketed sparse NMS -> sweep -> out.
// key = (sc-thr)<<15 | (32767-pos); order == (score desc, pos asc) == jax.
// Cold paths (64-bit bitonic / exact radix select) kept for robustness.
// ---------------------------------------------------------------------------
#define DYN_MASK   0          // u32[32768] bins -> later NMS mask (131072 B)
#define DYN_K2     131072     // ull[2048] / u32[2048] sorted keys   16384
#define DYN_K2B    147456     // ull[2048] / u32[2048] key stash     16384
#define DYN_X1     163840
#define DYN_Y1     167936
#define DYN_X2     172032
#define DYN_Y2     176128
#define DYN_AREA   180224
#define DYN_KIND   184320
#define DYN_LIST   188416
#define DYN_TOTAL  192512

__global__ void __launch_bounds__(1024, 1) fused_kernel(float* __restrict__ out) {
    extern __shared__ char smc[];
    u32*   s_mask   = (u32*)  (smc + DYN_MASK);     // bins, then NMS mask
    ull*   s_k2     = (ull*)  (smc + DYN_K2);
    ull*   s_k2b    = (ull*)  (smc + DYN_K2B);
    u32*   s_k32a   = (u32*)  (smc + DYN_K2);       // sorted keys (32-bit path)
    u32*   s_k32b   = (u32*)  (smc + DYN_K2B);      // stash (32-bit path)
    float* s_x1     = (float*)(smc + DYN_X1);
    float* s_y1     = (float*)(smc + DYN_Y1);
    float* s_x2     = (float*)(smc + DYN_X2);
    float* s_y2     = (float*)(smc + DYN_Y2);
    float* s_area   = (float*)(smc + DYN_AREA);
    int*   s_kindi  = (int*)  (smc + DYN_KIND);
    u32*   s_list   = (u32*)  (smc + DYN_LIST);

    __shared__ u32 s_h256[256];
    __shared__ u32 s_warp[32];
    __shared__ int s_cnt, s_digit, s_rem;
    __shared__ u32 s_ccnt[96], s_coff[96], s_cwr[96];
    __shared__ u32 s_rowany[1024];
    __shared__ u32 s_remw[32], s_diagany[32];

    int tid  = threadIdx.x;
    int lane = tid & 31;
    int wid  = tid >> 5;
    int b    = blockIdx.x;
    const u32* __restrict__ gs = g_score + (size_t)b * NPOS;

    // ---- init: zero bins (mask region), padding, flags ----
    {
        uint4* m4 = (uint4*)s_mask;
        #pragma unroll
        for (int i = 0; i < 8; i++) m4[tid + i * 1024] = make_uint4(0, 0, 0, 0);
    }
    s_rowany[tid] = 0;
    s_k2[tid] = 0; s_k2[tid + 1024] = 0;
    if (tid < 96) s_ccnt[tid] = 0;
    if (tid < 32) s_diagany[tid] = 0;

    // ---- global hist: 8 bins/thread in regs; re-zero; 2-barrier scan ----
    u32 h[8];
    {
        uint4* gh4 = (uint4*)(g_hist + (size_t)b * NBINS);
        uint4 h0 = gh4[tid * 2], h1 = gh4[tid * 2 + 1];
        gh4[tid * 2]     = make_uint4(0, 0, 0, 0);
        gh4[tid * 2 + 1] = make_uint4(0, 0, 0, 0);
        h[0] = h0.x; h[1] = h0.y; h[2] = h0.z; h[3] = h0.w;
        h[4] = h1.x; h[5] = h1.y; h[6] = h1.z; h[7] = h1.w;
    }
    {
        u32 suf[8];
        u32 run = 0;
        #pragma unroll
        for (int q = 7; q >= 0; q--) { run += h[q]; suf[q] = run; }
        u32 x = run;
        #pragma unroll
        for (int off = 1; off < 32; off <<= 1) {
            u32 y = __shfl_down_sync(FULLM, x, off);
            if (lane + off < 32) x += y;
        }
        u32 lanes_above = x - run;
        u32 wtot = __shfl_sync(FULLM, x, 0);
        if (lane == 0) s_warp[wid] = wtot;
        if (tid == 0) s_cnt = 0;
        __syncthreads();                                        // B1
        // redundant per-warp scan of the 32 warp totals (no extra barrier)
        u32 wv = s_warp[lane];
        u32 xx = wv;
        #pragma unroll
        for (int off = 1; off < 32; off <<= 1) {
            u32 y = __shfl_down_sync(FULLM, xx, off);
            if (lane + off < 32) xx += y;
        }
        u32 warps_above = __shfl_sync(FULLM, xx, wid) - wtot;
        u32 over = warps_above + lanes_above;
        #pragma unroll
        for (int q = 0; q < 8; q++) {
            u32 S = suf[q] + over;
            if (S >= (u32)KTOP && (S - h[q]) < (u32)KTOP) {
                s_digit = tid * 8 + q;
                s_rem   = (int)S;
            }
        }
    }
    __syncthreads();                                            // B2
    int bin     = s_digit;
    int candcnt = s_rem;
    u32 thr     = ((u32)(BASE_BIN + (u32)bin)) << HSHIFT;
    bool use32  = (candcnt <= CAP) && (thr >= 0x3F7E0000u);

    if (use32) {
        // ---- collect + inline key-bin histogram (stash unsorted keys) ----
        const uint4* __restrict__ g4 = (const uint4*)gs;
        for (int i = tid; i < NP4; i += 1024) {
            uint4 v = g4[i];
            u32 scs[4] = {v.x, v.y, v.z, v.w};
            #pragma unroll
            for (int e = 0; e < 4; e++) {
                u32 sc = scs[e];
                if (sc >= thr) {
                    int pos = i * 4 + e;
                    u32 k = ((sc - thr) << 15) | (u32)(32767 - pos);
                    atomicAdd(&s_mask[BSWZ(k >> 17)], 1u);
                    u32 act    = __activemask();
                    int rank   = __popc(act & ((1u << lane) - 1u));
                    int leader = __ffs(act) - 1;
                    int base   = 0;
                    if (lane == leader) base = atomicAdd(&s_cnt, __popc(act));
                    base = __shfl_sync(act, base, leader);
                    int slot = base + rank;
                    if (slot < CAP) s_k32b[slot] = k;
                }
            }
        }
        __syncthreads();                                        // B3
    } else if (candcnt <= CAP) {
        // ---- cold: collect 64-bit keys ----
        const uint4* __restrict__ g4 = (const uint4*)gs;
        for (int i = tid; i < NP4; i += 1024) {
            uint4 v = g4[i];
            u32 scs[4] = {v.x, v.y, v.z, v.w};
            #pragma unroll
            for (int e = 0; e < 4; e++) {
                u32 sc = scs[e];
                if (sc >= thr) {
                    int pos = i * 4 + e;
                    ull k = (((ull)sc) << 32) | (ull)(0xFFFFFFFFu - (u32)pos);
                    u32 act    = __activemask();
                    int rank   = __popc(act & ((1u << lane) - 1u));
                    int leader = __ffs(act) - 1;
                    int base   = 0;
                    if (lane == leader) base = atomicAdd(&s_cnt, __popc(act));
                    base = __shfl_sync(act, base, leader);
                    int slot = base + rank;
                    if (slot < CAP) s_k2[slot] = k;
                }
            }
        }
        __syncthreads();
    } else {
        // ---- fallback (pathological): exact 4-pass radix select ----
        u32* whall = (u32*)(smc + DYN_MASK);
        u32* wh    = whall + wid * 257;
        u32 prefix = 0;
        int remaining = KTOP;
        for (int shift = 24; shift >= 0; shift -= 8) {
            for (int i = tid; i < 32 * 257; i += 1024) whall[i] = 0;
            __syncthreads();
            u32 himask = (shift == 24) ? 0u : (~0u << (shift + 8));
            for (int i = tid; i < NPOS; i += 1024) {
                u32 sc = gs[i];
                if (shift == 24 || (sc & himask) == prefix) {
                    u32 d      = (sc >> shift) & 255u;
                    u32 act    = __activemask();
                    u32 peers  = __match_any_sync(act, d);
                    int leader = __ffs(peers) - 1;
                    if (lane == leader) wh[d] += (u32)__popc(peers);
                }
            }
            __syncthreads();
            if (tid < 256) {
                u32 t = 0;
                #pragma unroll
                for (int w = 0; w < 32; w++) t += whall[w * 257 + tid];
                s_h256[tid] = t;
            }
            __syncthreads();
            if (tid < 32) {
                u32 hh[8], sf[8];
                #pragma unroll
                for (int q = 0; q < 8; q++) hh[q] = s_h256[tid * 8 + q];
                u32 run = 0;
                #pragma unroll
                for (int q = 7; q >= 0; q--) { run += hh[q]; sf[q] = run; }
                u32 x = run;
                #pragma unroll
                for (int off = 1; off < 32; off <<= 1) {
                    u32 y = __shfl_down_sync(FULLM, x, off);
                    if (lane + off < 32) x += y;
                }
                u32 excl = x - run;
                #pragma unroll
                for (int q = 0; q < 8; q++) s_h256[tid * 8 + q] = sf[q] + excl;
            }
            __syncthreads();
            if (tid < 256) {
                u32 sfv  = s_h256[tid];
                u32 sfn  = (tid == 255) ? 0u : s_h256[tid + 1];
                if (sfv >= (u32)remaining && sfn < (u32)remaining) {
                    s_digit = tid;
                    s_rem   = remaining - (int)sfn;
                }
            }
            __syncthreads();
            prefix |= ((u32)s_digit) << shift;
            remaining = s_rem;
        }
        for (int i = tid; i < NPOS; i += 1024) {
            u32 sc = gs[i];
            if (sc >= prefix) {
                ull k = (((ull)sc) << 32) | (ull)(0xFFFFFFFFu - (u32)i);
                u32 act    = __activemask();
                int rank   = __popc(act & ((1u << lane) - 1u));
                int leader = __ffs(act) - 1;
                int base   = 0;
                if (lane == leader) base = atomicAdd(&s_cnt, __popc(act));
                base = __shfl_sync(act, base, leader);
                int slot = base + rank;
                if (slot < CAP) s_k2[slot] = k;
            }
        }
        __syncthreads();
    }

    u32 my_sc, my_idx;
    if (use32) {
        // ================= counting-rank sort (exact) =================
        int nc = s_cnt;
        // pass1: per-thread total over own 32 swizzled bins (conflict-free)
        u32 tt = 0;
        #pragma unroll
        for (int i = 0; i < 32; i++) tt += s_mask[32 * tid + (i ^ (tid & 31))];
        // block suffix-scan of totals (redundant-warp, 1 barrier)
        u32 x2 = tt;
        #pragma unroll
        for (int off = 1; off < 32; off <<= 1) {
            u32 y = __shfl_down_sync(FULLM, x2, off);
            if (lane + off < 32) x2 += y;
        }
        u32 lanes_above2 = x2 - tt;
        u32 wtot2 = __shfl_sync(FULLM, x2, 0);
        if (lane == 0) s_warp[wid] = wtot2;
        __syncthreads();                                        // B4
        u32 wv2 = s_warp[lane];
        u32 xx2 = wv2;
        #pragma unroll
        for (int off = 1; off < 32; off <<= 1) {
            u32 y = __shfl_down_sync(FULLM, xx2, off);
            if (lane + off < 32) xx2 += y;
        }
        u32 off_base = (__shfl_sync(FULLM, xx2, wid) - wtot2) + lanes_above2;
        // pass2: replace counts with (soff<<8), walking own bins high->low
        u32 acc = off_base;
        #pragma unroll
        for (int i = 31; i >= 0; i--) {
            int idx2 = 32 * tid + (i ^ (tid & 31));
            u32 c = s_mask[idx2];
            s_mask[idx2] = acc << 8;
            acc += c;
        }
        __syncthreads();                                        // B5
        // step A: scatter stash keys to rank slots
        u32 bin0 = 0, arr0 = 0, so0 = 0; bool v0 = (tid < nc);
        u32 bin1 = 0, arr1 = 0, so1 = 0; bool v1 = (tid + 1024 < nc);
        if (v0) {
            u32 k  = s_k32b[tid];
            bin0   = BSWZ(k >> 17);
            u32 o  = atomicAdd(&s_mask[bin0], 1u);
            so0    = o >> 8; arr0 = o & 0xFFu;
            s_k32a[so0 + arr0] = k;
        }
        if (v1) {
            u32 k  = s_k32b[tid + 1024];
            bin1   = BSWZ(k >> 17);
            u32 o  = atomicAdd(&s_mask[bin1], 1u);
            so1    = o >> 8; arr1 = o & 0xFFu;
            s_k32a[so1 + arr1] = k;
        }
        __syncthreads();                                        // B6
        // tie-fix: first arrival of each multi-key bin sorts its segment
        if (v0 && arr0 == 0) {
            u32 sz = s_mask[bin0] & 0xFFu;
            if (sz > 1) {
                for (u32 a = so0 + 1; a < so0 + sz; a++) {
                    u32 v = s_k32a[a]; u32 c = a;
                    while (c > so0 && s_k32a[c - 1] < v) { s_k32a[c] = s_k32a[c - 1]; c--; }
                    s_k32a[c] = v;
                }
            }
        }
        if (v1 && arr1 == 0) {
            u32 sz = s_mask[bin1] & 0xFFu;
            if (sz > 1) {
                for (u32 a = so1 + 1; a < so1 + sz; a++) {
                    u32 v = s_k32a[a]; u32 c = a;
                    while (c > so1 && s_k32a[c - 1] < v) { s_k32a[c] = s_k32a[c - 1]; c--; }
                    s_k32a[c] = v;
                }
            }
        }
        __syncthreads();                                        // B7
        u32 k  = s_k32a[tid];
        my_sc  = (k >> 15) + thr;
        my_idx = 32767u - (k & 0x7FFFu);
    } else {
        // ======= cold: 2048-key 64-bit bitonic sort (2 keys/thread) =======
        ull ka = s_k2[tid];
        ull kb = s_k2[tid + 1024];
        const int p1 = tid, p2 = tid + 1024;

        #pragma unroll
        for (int k2 = 2; k2 <= 32; k2 <<= 1) {
            #pragma unroll
            for (int j = k2 >> 1; j > 0; j >>= 1) {
                ull pa = __shfl_xor_sync(FULLM, ka, j);
                bool tA = (((p1 & k2) == 0) == ((p1 & j) == 0));
                ka = tA ? (ka > pa ? ka : pa) : (ka < pa ? ka : pa);
                ull pb = __shfl_xor_sync(FULLM, kb, j);
                bool tB = (((p2 & k2) == 0) == ((p2 & j) == 0));
                kb = tB ? (kb > pb ? kb : pb) : (kb < pb ? kb : pb);
            }
        }
        int parity = 1;
        for (int k2 = 64; k2 <= 2048; k2 <<= 1) {
            for (int j = k2 >> 1; j >= 32; j >>= 1) {
                if (j == 1024) {
                    ull mx = ka > kb ? ka : kb;
                    ull mn = ka < kb ? ka : kb;
                    ka = mx; kb = mn;
                } else {
                    ull* wb = parity ? s_k2b : s_k2;
                    parity ^= 1;
                    wb[tid] = ka;
                    wb[tid + 1024] = kb;
                    __syncthreads();
                    ull pa = wb[tid ^ j];
                    ull pb = wb[(tid ^ j) + 1024];
                    bool tA = (((p1 & k2) == 0) == ((p1 & j) == 0));
                    ka = tA ? (ka > pa ? ka : pa) : (ka < pa ? ka : pa);
                    bool tB = (((p2 & k2) == 0) == ((p2 & j) == 0));
                    kb = tB ? (kb > pb ? kb : pb) : (kb < pb ? kb : pb);
                }
            }
            #pragma unroll
            for (int j = 16; j > 0; j >>= 1) {
                ull pa = __shfl_xor_sync(FULLM, ka, j);
                bool tA = (((p1 & k2) == 0) == ((p1 & j) == 0));
                ka = tA ? (ka > pa ? ka : pa) : (ka < pa ? ka : pa);
                ull pb = __shfl_xor_sync(FULLM, kb, j);
                bool tB = (((p2 & k2) == 0) == ((p2 & j) == 0));
                kb = tB ? (kb > pb ? kb : pb) : (kb < pb ? kb : pb);
            }
        }
        my_sc  = (u32)(ka >> 32);
        my_idx = 0xFFFFFFFFu - (u32)(ka & 0xFFFFFFFFull);
    }
    // (my_sc, my_idx) = score bits + position at sorted rank tid (descending)

    // ---- zero the NMS mask (bins region dead; next barrier covers) ----
    {
        uint4* m4 = (uint4*)s_mask;
        #pragma unroll
        for (int i = 0; i < 8; i++) m4[tid + i * 1024] = make_uint4(0, 0, 0, 0);
    }

    // ---- gather boxes + count classes (match-dedup'd atomics) ----
    int myk_cls = -1;
    {
        float4 bx = make_float4(0.f, 0.f, 0.f, 0.f);
        if (tid < KTOP) {
            bx = g_boxes[(size_t)b * NPOS + my_idx];
            myk_cls = (int)g_kind[(size_t)b * NPOS + my_idx];
            u32 act    = __activemask();
            u32 peers  = __match_any_sync(act, myk_cls);
            int leader = __ffs(peers) - 1;
            if (lane == leader) atomicAdd(&s_ccnt[myk_cls], (u32)__popc(peers));
        }
        s_x1[tid] = bx.x; s_y1[tid] = bx.y; s_x2[tid] = bx.z; s_y2[tid] = bx.w;
        s_kindi[tid] = myk_cls;
        s_area[tid] = fmaxf(bx.z - bx.x, 0.f) * fmaxf(bx.w - bx.y, 0.f);
    }
    __syncthreads();                                            // B8

    // ---- exclusive prefix over 80 (padded 96) class counts: warp 0 ----
    if (tid < 32) {
        int c0 = tid * 3;
        u32 a0 = s_ccnt[c0], a1 = s_ccnt[c0 + 1], a2 = s_ccnt[c0 + 2];
        u32 tot3 = a0 + a1 + a2;
        u32 x = tot3;
        #pragma unroll
        for (int off = 1; off < 32; off <<= 1) {
            u32 y = __shfl_up_sync(FULLM, x, off);
            if (lane >= off) x += y;
        }
        u32 excl = x - tot3;
        s_coff[c0]     = excl;           s_cwr[c0]     = excl;
        s_coff[c0 + 1] = excl + a0;      s_cwr[c0 + 1] = excl + a0;
        s_coff[c0 + 2] = excl + a0 + a1; s_cwr[c0 + 2] = excl + a0 + a1;
    }
    __syncthreads();                                            // B9

    // ---- scatter into class lists (match-dedup'd) ----
    int myrank = 0;
    if (tid < KTOP) {
        u32 act    = __activemask();
        u32 peers  = __match_any_sync(act, myk_cls);
        int leader = __ffs(peers) - 1;
        u32 prior  = (u32)__popc(peers & ((1u << lane) - 1u));
        u32 base   = 0;
        if (lane == leader) base = atomicAdd(&s_cwr[myk_cls], (u32)__popc(peers));
        base = __shfl_sync(act, base, leader);
        u32 slot = base + prior;
        myrank = (int)(slot - s_coff[myk_cls]);
        s_list[slot] = (u32)tid;
    }
    __syncthreads();                                            // B10

    // ---- same-class pair compare -> sparse mask bits + flags ----
    if (tid < KTOP) {
        int off = (int)s_coff[myk_cls];
        int n   = (int)s_cwr[myk_cls] - off;
        float bx1 = s_x1[tid], by1 = s_y1[tid], bx2 = s_x2[tid], by2 = s_y2[tid];
        for (int r = myrank + 1; r < n; r++) {
            int o = (int)s_list[off + r];
            float xx1 = fmaxf(bx1, s_x1[o]);
            float yy1 = fmaxf(by1, s_y1[o]);
            float xx2 = fminf(bx2, s_x2[o]);
            float yy2 = fminf(by2, s_y2[o]);
            float inter = fmaxf(xx2 - xx1, 0.f) * fmaxf(yy2 - yy1, 0.f);
            int i = min(tid, o), j = max(tid, o);
            float denom = s_area[i] + s_area[j] - inter + 1e-9f;
            if (inter > 0.5f * denom) {
                atomicOr(&s_mask[i * 32 + (j >> 5)], 1u << (j & 31));
                atomicOr(&s_rowany[i], 1u);
                if ((i >> 5) == (j >> 5)) atomicOr(&s_diagany[i >> 5], 1u);
            }
        }
    }
    __syncthreads();                                            // B11

    // ---- sparsity-aware serial sweep on warp 0 ----
    if (tid < 32) {
        u32 rem = 0;
        for (int c = 0; c < 32; c++) {
            u32 ra = s_rowany[c * 32 + lane];
            if (__reduce_or_sync(FULLM, ra) == 0u) continue;
            u32 cur = __shfl_sync(FULLM, rem, c);
            if (s_diagany[c] == 0u) {
                u32 K = ~cur;
                u32 a0 = 0, a1 = 0, a2 = 0, a3 = 0;
                #pragma unroll
                for (int k = 0; k < 32; k += 4) {
                    a0 |= s_mask[(c * 32 + k    ) * 32 + lane] & (u32)(((int)(K << (31 - k)))       >> 31);
                    a1 |= s_mask[(c * 32 + k + 1) * 32 + lane] & (u32)(((int)(K << (31 - (k + 1)))) >> 31);
                    a2 |= s_mask[(c * 32 + k + 2) * 32 + lane] & (u32)(((int)(K << (31 - (k + 2)))) >> 31);
                    a3 |= s_mask[(c * 32 + k + 3) * 32 + lane] & (u32)(((int)(K << (31 - (k + 3)))) >> 31);
                }
                rem |= (a0 | a1) | (a2 | a3);
            } else {
                u32 acc = 0;
                #pragma unroll 4
                for (int k = 0; k < 32; k++) {
                    if (!((cur >> k) & 1u)) {
                        acc |= s_mask[(c * 32 + k) * 32 + lane];
                        cur |= s_mask[(c * 32 + k) * 32 + c];
                    }
                }
                rem |= acc;
            }
        }
        s_remw[lane] = rem;
    }
    __syncthreads();                                            // B12

    // ---- output ----
    if (tid < KTOP) {
        bool removed = (s_remw[tid >> 5] >> (tid & 31)) & 1u;
        float sc = __uint_as_float(my_sc);
        float out_sc = (!removed && sc > 0.0f) ? sc : 0.0f;
        float* op = out + ((size_t)b * KTOP + tid) * 6;
        op[0] = s_x1[tid]; op[1] = s_y1[tid]; op[2] = s_x2[tid]; op[3] = s_y2[tid];
        op[4] = (float)s_kindi[tid];
        op[5] = out_sc;
    }
}

// ---------------------------------------------------------------------------
extern "C" void kernel_launch(void* const* d_in, const int* in_sizes, int n_in,
                              void* d_out, int out_size) {
    bool dict_order = (in_sizes[1] != 2621440);
    Ptrs p;
    for (int i = 0; i < 5; i++) {
        if (dict_order) {
            p.cls[i] = (const float*)d_in[3 * i];
            p.reg[i] = (const float*)d_in[3 * i + 2];
        } else {
            p.cls[i] = (const float*)d_in[i];
            p.reg[i] = (const float*)d_in[10 + i];
        }
    }

    int total = BATCH * NPOS;
    decode_kernel<<<(total + 255) / 256, 256>>>(p);

    cudaFuncSetAttribute(fused_kernel,
                         cudaFuncAttributeMaxDynamicSharedMemorySize, DYN_TOTAL);
    fused_kernel<<<BATCH, 1024, DYN_TOTAL>>>((float*)d_out);
}

// round 17
// speedup vs baseline: 1.4476x; 1.4476x over previous
#include <cuda_runtime.h>

typedef unsigned long long ull;
typedef unsigned int u32;

#define NPOS   21824
#define NP4    (NPOS / 4)          // 5456
#define BATCH  8
#define KTOP   1000
#define NCLS   80
#define FULLM  0xffffffffu
#define NBINS  8192
#define HSHIFT 12
#define BASE_BIN 0x3D800u          // 0x3D800000 >> 12  (score 0.0625)
#define CAP    2048

// Scratch (no allocation allowed -> __device__ globals)
__device__ u32    g_score[BATCH * NPOS];
__device__ float4 g_boxes[BATCH * NPOS];
__device__ float  g_kind[BATCH * NPOS];
__device__ u32    g_hist[BATCH * NBINS];   // zero-init; consumed+re-zeroed by fused

__constant__ int   c_off[5]    = {0, 16384, 20480, 21504, 21760};
__constant__ int   c_logw[5]   = {7, 6, 5, 4, 3};
__constant__ float c_stride[5] = {8.f, 16.f, 32.f, 64.f, 128.f};

struct Ptrs { const float* cls[5]; const float* reg[5]; };

// ---------------------------------------------------------------------------
// Kernel 1: decode -> (score bits, box, kind) + global score histogram
// ---------------------------------------------------------------------------
__global__ void decode_kernel(Ptrs p) {
    int gid = blockIdx.x * blockDim.x + threadIdx.x;
    if (gid >= BATCH * NPOS) return;
    int b   = gid / NPOS;
    int pos = gid - b * NPOS;

    int lev = 0;
    if      (pos >= c_off[4]) lev = 4;
    else if (pos >= c_off[3]) lev = 3;
    else if (pos >= c_off[2]) lev = 2;
    else if (pos >= c_off[1]) lev = 1;

    int local = pos - c_off[lev];
    int lw = c_logw[lev];
    int w  = 1 << lw;
    int hw = w * w;
    int y  = local >> lw;
    int x  = local & (w - 1);

    const float* __restrict__ cbase = p.cls[lev] + (size_t)b * NCLS * hw + local;
    float best = cbase[0];
    int   bi   = 0;
    #pragma unroll 16
    for (int c = 1; c < NCLS; c++) {
        float v = cbase[(size_t)c * hw];
        if (v > best) { best = v; bi = c; }
    }
    float score = (best > 0.05f) ? best : 0.0f;

    const float* __restrict__ rbase = p.reg[lev] + (size_t)b * 4 * hw + local;
    float s  = c_stride[lev];
    float r0 = rbase[0]      * s;
    float r1 = rbase[hw]     * s;
    float r2 = rbase[2 * hw] * s;
    float r3 = rbase[3 * hw] * s;
    float cx = ((float)x + 0.5f) * s;
    float cy = ((float)y + 0.5f) * s;

    g_boxes[gid] = make_float4(cx - r0, cy - r1, cx + r2, cy + r3);
    g_kind[gid]  = (float)bi;
    u32 sb = __float_as_uint(score);
    g_score[gid] = sb;

    int idx = (int)(sb >> HSHIFT) - (int)BASE_BIN;
    idx = idx < 0 ? 0 : (idx > NBINS - 1 ? NBINS - 1 : idx);
    atomicAdd(&g_hist[b * NBINS + idx], 1u);
}

// ---------------------------------------------------------------------------
// Kernel 2 (FUSED): per-image block.
//   hist suffix-scan -> binfloor -> collect scan (+64-bin boundary sub-hist)
//   -> sub-threshold refinement (cand2 <= 1024) -> compact ->
//   1024-key 32-bit bitonic (identity ownership; main path)
//   or 2048-key 32-bit sort / 64-bit sort / exact radix (cold) ->
//   class-bucketed sparse NMS -> sparsity-aware sweep -> output.
// key = (sc-thr)<<15 | (32767-pos); order == (score desc, pos asc) == jax.
// ---------------------------------------------------------------------------
#define DYN_MASK   0          // u32[1024*32] 131072 (also fallback wh scratch)
#define DYN_K2     131072     // ull[2048] / u32[2048] sort buf A   16384
#define DYN_K2B    147456     // ull[2048] / u32[2048] stash/buf B  16384
#define DYN_X1     163840
#define DYN_Y1     167936
#define DYN_X2     172032
#define DYN_Y2     176128
#define DYN_AREA   180224
#define DYN_KIND   184320
#define DYN_LIST   188416
#define DYN_TOTAL  192512

__global__ void __launch_bounds__(1024, 1) fused_kernel(float* __restrict__ out) {
    extern __shared__ char smc[];
    u32*   s_mask   = (u32*)  (smc + DYN_MASK);
    ull*   s_k2     = (ull*)  (smc + DYN_K2);
    ull*   s_k2b    = (ull*)  (smc + DYN_K2B);
    u32*   s_k32a   = (u32*)  (smc + DYN_K2);    // 32-bit views (2048 u32 each)
    u32*   s_k32b   = (u32*)  (smc + DYN_K2B);
    float* s_x1     = (float*)(smc + DYN_X1);
    float* s_y1     = (float*)(smc + DYN_Y1);
    float* s_x2     = (float*)(smc + DYN_X2);
    float* s_y2     = (float*)(smc + DYN_Y2);
    float* s_area   = (float*)(smc + DYN_AREA);
    int*   s_kindi  = (int*)  (smc + DYN_KIND);
    u32*   s_list   = (u32*)  (smc + DYN_LIST);

    __shared__ u32 s_h256[256];
    __shared__ u32 s_warp[32];
    __shared__ u32 s_sub[64];
    __shared__ int s_cnt, s_cnt2, s_digit, s_rem;
    __shared__ u32 s_ccnt[96], s_coff[96], s_cwr[96];
    __shared__ u32 s_rowany[1024];
    __shared__ u32 s_remw[32], s_diagany[32];

    int tid  = threadIdx.x;
    int lane = tid & 31;
    int wid  = tid >> 5;
    int b    = blockIdx.x;
    const u32* __restrict__ gs = g_score + (size_t)b * NPOS;

    // ---- init ----
    s_rowany[tid] = 0;
    s_k2[tid]  = 0; s_k2[tid + 1024]  = 0;    // buf A (incl. 32-bit view + pad)
    s_k2b[tid] = 0; s_k2b[tid + 1024] = 0;    // stash zero-pad
    if (tid < 96) s_ccnt[tid] = 0;
    if (tid < 64) s_sub[tid] = 0;
    if (tid < 32) s_diagany[tid] = 0;

    // ---- global hist: 8 bins/thread (32B lane stride); re-zero; 2-barrier scan ----
    u32 h[8];
    {
        uint4* gh4 = (uint4*)(g_hist + (size_t)b * NBINS);
        uint4 h0 = gh4[tid * 2], h1 = gh4[tid * 2 + 1];
        gh4[tid * 2]     = make_uint4(0, 0, 0, 0);
        gh4[tid * 2 + 1] = make_uint4(0, 0, 0, 0);
        h[0] = h0.x; h[1] = h0.y; h[2] = h0.z; h[3] = h0.w;
        h[4] = h1.x; h[5] = h1.y; h[6] = h1.z; h[7] = h1.w;
    }
    {
        u32 suf[8];
        u32 run = 0;
        #pragma unroll
        for (int q = 7; q >= 0; q--) { run += h[q]; suf[q] = run; }
        u32 x = run;
        #pragma unroll
        for (int off = 1; off < 32; off <<= 1) {
            u32 y = __shfl_down_sync(FULLM, x, off);
            if (lane + off < 32) x += y;
        }
        u32 lanes_above = x - run;
        u32 wtot = __shfl_sync(FULLM, x, 0);
        if (lane == 0) s_warp[wid] = wtot;
        if (tid == 0) { s_cnt = 0; s_cnt2 = 0; }
        __syncthreads();                                        // B1
        // redundant per-warp scan of the 32 warp totals (no extra barrier)
        u32 wv = s_warp[lane];
        u32 xx = wv;
        #pragma unroll
        for (int off = 1; off < 32; off <<= 1) {
            u32 y = __shfl_down_sync(FULLM, xx, off);
            if (lane + off < 32) xx += y;
        }
        u32 warps_above = __shfl_sync(FULLM, xx, wid) - wtot;
        u32 over = warps_above + lanes_above;
        #pragma unroll
        for (int q = 0; q < 8; q++) {
            u32 S = suf[q] + over;
            if (S >= (u32)KTOP && (S - h[q]) < (u32)KTOP) {
                s_digit = tid * 8 + q;
                s_rem   = (int)S;
            }
        }
    }
    __syncthreads();                                            // B2
    int bin     = s_digit;
    int candcnt = s_rem;
    u32 thr     = ((u32)(BASE_BIN + (u32)bin)) << HSHIFT;
    bool use32  = (candcnt <= CAP) && (thr >= 0x3F7E0000u);

    u32 my_sc, my_idx;
    if (use32) {
        // ---- collect to stash + 64-bin boundary sub-hist ----
        const uint4* __restrict__ g4 = (const uint4*)gs;
        for (int i = tid; i < NP4; i += 1024) {
            uint4 v = g4[i];
            u32 scs[4] = {v.x, v.y, v.z, v.w};
            #pragma unroll
            for (int e = 0; e < 4; e++) {
                u32 sc = scs[e];
                if (sc >= thr) {
                    int pos = i * 4 + e;
                    u32 d = sc - thr;
                    if (d < 4096u) atomicAdd(&s_sub[d >> 6], 1u);
                    u32 k = (d << 15) | (u32)(32767 - pos);
                    u32 act    = __activemask();
                    int rank   = __popc(act & ((1u << lane) - 1u));
                    int leader = __ffs(act) - 1;
                    int base   = 0;
                    if (lane == leader) base = atomicAdd(&s_cnt, __popc(act));
                    base = __shfl_sync(act, base, leader);
                    int slot = base + rank;
                    if (slot < CAP) s_k32b[slot] = k;
                }
            }
        }
        __syncthreads();                                        // B3

        // ---- sub-threshold refinement (redundant per warp, no barrier) ----
        u32 c0 = s_sub[lane];            // sub-bin = lane
        u32 c1 = s_sub[lane + 32];       // sub-bin = lane + 32
        // suffix over high bins: suf1(lane) = sum_{p>=lane} c1
        u32 x1 = c1;
        #pragma unroll
        for (int off = 1; off < 32; off <<= 1) {
            u32 y = __shfl_down_sync(FULLM, x1, off);
            if (lane + off < 32) x1 += y;
        }
        u32 tot1 = __shfl_sync(FULLM, x1, 0);
        u32 x0 = c0;
        #pragma unroll
        for (int off = 1; off < 32; off <<= 1) {
            u32 y = __shfl_down_sync(FULLM, x0, off);
            if (lane + off < 32) x0 += y;
        }
        u32 tot0  = __shfl_sync(FULLM, x0, 0);
        u32 n_hi  = (u32)candcnt - (tot0 + tot1);     // above boundary bin
        u32 Sh    = n_hi + x1;                        // S(t = lane+32)
        u32 Sl    = n_hi + tot1 + x0;                 // S(t = lane)
        u32 bm_hi = __ballot_sync(FULLM, Sh >= (u32)KTOP && (Sh - c1) < (u32)KTOP);
        u32 bm_lo = __ballot_sync(FULLM, Sl >= (u32)KTOP && (Sl - c0) < (u32)KTOP);
        u32 tstar, cand2;
        if (bm_hi) {
            int l = __ffs(bm_hi) - 1;
            tstar = 32u + (u32)l;
            cand2 = __shfl_sync(FULLM, Sh, l);
        } else {
            int l = __ffs(bm_lo) - 1;
            tstar = (u32)l;
            cand2 = __shfl_sync(FULLM, Sl, l);
        }
        u32 Kstar = tstar << 21;

        if (cand2 <= 1024u) {
            // ---- compact stash -> s_k32a (zero-padded), then 1024-key sort ----
            int nc = s_cnt;
            for (int i = tid; i < nc; i += 1024) {
                u32 k = s_k32b[i];
                if (k >= Kstar) {
                    u32 act    = __activemask();
                    int rank   = __popc(act & ((1u << lane) - 1u));
                    int leader = __ffs(act) - 1;
                    int base   = 0;
                    if (lane == leader) base = atomicAdd(&s_cnt2, __popc(act));
                    base = __shfl_sync(act, base, leader);
                    s_k32a[base + rank] = k;
                }
            }
            __syncthreads();                                    // B4

            // 1024-key bitonic, descending; position = tid (identity ownership)
            u32 kk = s_k32a[tid];
            #pragma unroll
            for (int k2 = 2; k2 <= 32; k2 <<= 1) {
                #pragma unroll
                for (int j = k2 >> 1; j > 0; j >>= 1) {
                    u32 pk = __shfl_xor_sync(FULLM, kk, j);
                    bool tA = (((tid & k2) == 0) == ((tid & j) == 0));
                    kk = tA ? (kk > pk ? kk : pk) : (kk < pk ? kk : pk);
                }
            }
            int parity = 0;
            for (int k2 = 64; k2 <= 1024; k2 <<= 1) {
                for (int j = k2 >> 1; j >= 32; j >>= 1) {
                    u32* wb = parity ? s_k32b : s_k32a;
                    parity ^= 1;
                    wb[tid] = kk;
                    __syncthreads();
                    u32 pk = wb[tid ^ j];
                    bool tA = (((tid & k2) == 0) == ((tid & j) == 0));
                    kk = tA ? (kk > pk ? kk : pk) : (kk < pk ? kk : pk);
                }
                #pragma unroll
                for (int j = 16; j > 0; j >>= 1) {
                    u32 pk = __shfl_xor_sync(FULLM, kk, j);
                    bool tA = (((tid & k2) == 0) == ((tid & j) == 0));
                    kk = tA ? (kk > pk ? kk : pk) : (kk < pk ? kk : pk);
                }
            }
            my_sc  = (kk >> 15) + thr;
            my_idx = 32767u - (kk & 0x7FFFu);
        } else {
            // ---- rare: 2048-key 32-bit bitonic on the stash (R15 path) ----
            const int p1 = (wid << 6) + lane;
            const int p2 = p1 + 32;
            u32 ka = s_k32b[p1];
            u32 kb = s_k32b[p2];

            #pragma unroll
            for (int k2 = 2; k2 <= 32; k2 <<= 1) {
                #pragma unroll
                for (int j = k2 >> 1; j > 0; j >>= 1) {
                    u32 pa = __shfl_xor_sync(FULLM, ka, j);
                    bool tA = (((p1 & k2) == 0) == ((p1 & j) == 0));
                    ka = tA ? (ka > pa ? ka : pa) : (ka < pa ? ka : pa);
                    u32 pb = __shfl_xor_sync(FULLM, kb, j);
                    bool tB = (((p2 & k2) == 0) == ((p2 & j) == 0));
                    kb = tB ? (kb > pb ? kb : pb) : (kb < pb ? kb : pb);
                }
            }
            int parity = 0;
            for (int k2 = 64; k2 <= 2048; k2 <<= 1) {
                for (int j = k2 >> 1; j >= 64; j >>= 1) {
                    u32* wb = parity ? s_k32b : s_k32a;
                    parity ^= 1;
                    wb[p1] = ka;
                    wb[p2] = kb;
                    __syncthreads();
                    u32 pa = wb[p1 ^ j];
                    u32 pb = wb[p2 ^ j];
                    bool tA = (((p1 & k2) == 0) == ((p1 & j) == 0));
                    ka = tA ? (ka > pa ? ka : pa) : (ka < pa ? ka : pa);
                    bool tB = (((p2 & k2) == 0) == ((p2 & j) == 0));
                    kb = tB ? (kb > pb ? kb : pb) : (kb < pb ? kb : pb);
                }
                {   // j = 32: in-thread
                    bool tA = ((p1 & k2) == 0);
                    u32 mx = ka > kb ? ka : kb;
                    u32 mn = ka < kb ? ka : kb;
                    ka = tA ? mx : mn;
                    kb = tA ? mn : mx;
                }
                #pragma unroll
                for (int j = 16; j > 0; j >>= 1) {
                    u32 pa = __shfl_xor_sync(FULLM, ka, j);
                    bool tA = (((p1 & k2) == 0) == ((p1 & j) == 0));
                    ka = tA ? (ka > pa ? ka : pa) : (ka < pa ? ka : pa);
                    u32 pb = __shfl_xor_sync(FULLM, kb, j);
                    bool tB = (((p2 & k2) == 0) == ((p2 & j) == 0));
                    kb = tB ? (kb > pb ? kb : pb) : (kb < pb ? kb : pb);
                }
            }
            {
                u32* wb = parity ? s_k32b : s_k32a;
                wb[p1] = ka;
                wb[p2] = kb;
                __syncthreads();
                u32 k = wb[tid];
                my_sc  = (k >> 15) + thr;
                my_idx = 32767u - (k & 0x7FFFu);
            }
        }
    } else if (candcnt <= CAP) {
        // ---- cold: collect + 2048-key 64-bit bitonic ----
        const uint4* __restrict__ g4 = (const uint4*)gs;
        for (int i = tid; i < NP4; i += 1024) {
            uint4 v = g4[i];
            u32 scs[4] = {v.x, v.y, v.z, v.w};
            #pragma unroll
            for (int e = 0; e < 4; e++) {
                u32 sc = scs[e];
                if (sc >= thr) {
                    int pos = i * 4 + e;
                    ull k = (((ull)sc) << 32) | (ull)(0xFFFFFFFFu - (u32)pos);
                    u32 act    = __activemask();
                    int rank   = __popc(act & ((1u << lane) - 1u));
                    int leader = __ffs(act) - 1;
                    int base   = 0;
                    if (lane == leader) base = atomicAdd(&s_cnt, __popc(act));
                    base = __shfl_sync(act, base, leader);
                    int slot = base + rank;
                    if (slot < CAP) s_k2[slot] = k;
                }
            }
        }
        __syncthreads();

        ull ka = s_k2[tid];
        ull kb = s_k2[tid + 1024];
        const int p1 = tid, p2 = tid + 1024;
        #pragma unroll
        for (int k2 = 2; k2 <= 32; k2 <<= 1) {
            #pragma unroll
            for (int j = k2 >> 1; j > 0; j >>= 1) {
                ull pa = __shfl_xor_sync(FULLM, ka, j);
                bool tA = (((p1 & k2) == 0) == ((p1 & j) == 0));
                ka = tA ? (ka > pa ? ka : pa) : (ka < pa ? ka : pa);
                ull pb = __shfl_xor_sync(FULLM, kb, j);
                bool tB = (((p2 & k2) == 0) == ((p2 & j) == 0));
                kb = tB ? (kb > pb ? kb : pb) : (kb < pb ? kb : pb);
            }
        }
        int parity = 1;
        for (int k2 = 64; k2 <= 2048; k2 <<= 1) {
            for (int j = k2 >> 1; j >= 32; j >>= 1) {
                if (j == 1024) {
                    ull mx = ka > kb ? ka : kb;
                    ull mn = ka < kb ? ka : kb;
                    ka = mx; kb = mn;
                } else {
                    ull* wb = parity ? s_k2b : s_k2;
                    parity ^= 1;
                    wb[tid] = ka;
                    wb[tid + 1024] = kb;
                    __syncthreads();
                    ull pa = wb[tid ^ j];
                    ull pb = wb[(tid ^ j) + 1024];
                    bool tA = (((p1 & k2) == 0) == ((p1 & j) == 0));
                    ka = tA ? (ka > pa ? ka : pa) : (ka < pa ? ka : pa);
                    bool tB = (((p2 & k2) == 0) == ((p2 & j) == 0));
                    kb = tB ? (kb > pb ? kb : pb) : (kb < pb ? kb : pb);
                }
            }
            #pragma unroll
            for (int j = 16; j > 0; j >>= 1) {
                ull pa = __shfl_xor_sync(FULLM, ka, j);
                bool tA = (((p1 & k2) == 0) == ((p1 & j) == 0));
                ka = tA ? (ka > pa ? ka : pa) : (ka < pa ? ka : pa);
                ull pb = __shfl_xor_sync(FULLM, kb, j);
                bool tB = (((p2 & k2) == 0) == ((p2 & j) == 0));
                kb = tB ? (kb > pb ? kb : pb) : (kb < pb ? kb : pb);
            }
        }
        my_sc  = (u32)(ka >> 32);
        my_idx = 0xFFFFFFFFu - (u32)(ka & 0xFFFFFFFFull);
    } else {
        // ---- fallback (pathological): exact 4-pass radix select + 64-bit sort keyless fill ----
        u32* whall = (u32*)(smc + DYN_MASK);
        u32* wh    = whall + wid * 257;
        u32 prefix = 0;
        int remaining = KTOP;
        for (int shift = 24; shift >= 0; shift -= 8) {
            for (int i = tid; i < 32 * 257; i += 1024) whall[i] = 0;
            __syncthreads();
            u32 himask = (shift == 24) ? 0u : (~0u << (shift + 8));
            for (int i = tid; i < NPOS; i += 1024) {
                u32 sc = gs[i];
                if (shift == 24 || (sc & himask) == prefix) {
                    u32 d      = (sc >> shift) & 255u;
                    u32 act    = __activemask();
                    u32 peers  = __match_any_sync(act, d);
                    int leader = __ffs(peers) - 1;
                    if (lane == leader) wh[d] += (u32)__popc(peers);
                }
            }
            __syncthreads();
            if (tid < 256) {
                u32 t = 0;
                #pragma unroll
                for (int w = 0; w < 32; w++) t += whall[w * 257 + tid];
                s_h256[tid] = t;
            }
            __syncthreads();
            if (tid < 32) {
                u32 hh[8], sf[8];
                #pragma unroll
                for (int q = 0; q < 8; q++) hh[q] = s_h256[tid * 8 + q];
                u32 run = 0;
                #pragma unroll
                for (int q = 7; q >= 0; q--) { run += hh[q]; sf[q] = run; }
                u32 x = run;
                #pragma unroll
                for (int off = 1; off < 32; off <<= 1) {
                    u32 y = __shfl_down_sync(FULLM, x, off);
                    if (lane + off < 32) x += y;
                }
                u32 excl = x - run;
                #pragma unroll
                for (int q = 0; q < 8; q++) s_h256[tid * 8 + q] = sf[q] + excl;
            }
            __syncthreads();
            if (tid < 256) {
                u32 sfv  = s_h256[tid];
                u32 sfn  = (tid == 255) ? 0u : s_h256[tid + 1];
                if (sfv >= (u32)remaining && sfn < (u32)remaining) {
                    s_digit = tid;
                    s_rem   = remaining - (int)sfn;
                }
            }
            __syncthreads();
            prefix |= ((u32)s_digit) << shift;
            remaining = s_rem;
        }
        for (int i = tid; i < NPOS; i += 1024) {
            u32 sc = gs[i];
            if (sc >= prefix) {
                ull k = (((ull)sc) << 32) | (ull)(0xFFFFFFFFu - (u32)i);
                u32 act    = __activemask();
                int rank   = __popc(act & ((1u << lane) - 1u));
                int leader = __ffs(act) - 1;
                int base   = 0;
                if (lane == leader) base = atomicAdd(&s_cnt, __popc(act));
                base = __shfl_sync(act, base, leader);
                int slot = base + rank;
                if (slot < CAP) s_k2[slot] = k;
            }
        }
        __syncthreads();
        // sort the (<=2048) selected keys with the 64-bit bitonic
        ull ka = s_k2[tid];
        ull kb = s_k2[tid + 1024];
        const int p1 = tid, p2 = tid + 1024;
        #pragma unroll
        for (int k2 = 2; k2 <= 32; k2 <<= 1) {
            #pragma unroll
            for (int j = k2 >> 1; j > 0; j >>= 1) {
                ull pa = __shfl_xor_sync(FULLM, ka, j);
                bool tA = (((p1 & k2) == 0) == ((p1 & j) == 0));
                ka = tA ? (ka > pa ? ka : pa) : (ka < pa ? ka : pa);
                ull pb = __shfl_xor_sync(FULLM, kb, j);
                bool tB = (((p2 & k2) == 0) == ((p2 & j) == 0));
                kb = tB ? (kb > pb ? kb : pb) : (kb < pb ? kb : pb);
            }
        }
        int parity = 1;
        for (int k2 = 64; k2 <= 2048; k2 <<= 1) {
            for (int j = k2 >> 1; j >= 32; j >>= 1) {
                if (j == 1024) {
                    ull mx = ka > kb ? ka : kb;
                    ull mn = ka < kb ? ka : kb;
                    ka = mx; kb = mn;
                } else {
                    ull* wb = parity ? s_k2b : s_k2;
                    parity ^= 1;
                    wb[tid] = ka;
                    wb[tid + 1024] = kb;
                    __syncthreads();
                    ull pa = wb[tid ^ j];
                    ull pb = wb[(tid ^ j) + 1024];
                    bool tA = (((p1 & k2) == 0) == ((p1 & j) == 0));
                    ka = tA ? (ka > pa ? ka : pa) : (ka < pa ? ka : pa);
                    bool tB = (((p2 & k2) == 0) == ((p2 & j) == 0));
                    kb = tB ? (kb > pb ? kb : pb) : (kb < pb ? kb : pb);
                }
            }
            #pragma unroll
            for (int j = 16; j > 0; j >>= 1) {
                ull pa = __shfl_xor_sync(FULLM, ka, j);
                bool tA = (((p1 & k2) == 0) == ((p1 & j) == 0));
                ka = tA ? (ka > pa ? ka : pa) : (ka < pa ? ka : pa);
                ull pb = __shfl_xor_sync(FULLM, kb, j);
                bool tB = (((p2 & k2) == 0) == ((p2 & j) == 0));
                kb = tB ? (kb > pb ? kb : pb) : (kb < pb ? kb : pb);
            }
        }
        my_sc  = (u32)(ka >> 32);
        my_idx = 0xFFFFFFFFu - (u32)(ka & 0xFFFFFFFFull);
    }
    // (my_sc, my_idx) = score bits + position at sorted rank tid (descending)

    // ---- zero the NMS mask (fallback scratch dead; barriers below cover) ----
    {
        uint4* m4 = (uint4*)s_mask;
        #pragma unroll
        for (int i = 0; i < 8; i++) m4[tid + i * 1024] = make_uint4(0, 0, 0, 0);
    }

    // ---- gather boxes + count classes (match-dedup'd atomics) ----
    int myk_cls = -1;
    {
        float4 bx = make_float4(0.f, 0.f, 0.f, 0.f);
        if (tid < KTOP) {
            bx = g_boxes[(size_t)b * NPOS + my_idx];
            myk_cls = (int)g_kind[(size_t)b * NPOS + my_idx];
            u32 act    = __activemask();
            u32 peers  = __match_any_sync(act, myk_cls);
            int leader = __ffs(peers) - 1;
            if (lane == leader) atomicAdd(&s_ccnt[myk_cls], (u32)__popc(peers));
        }
        s_x1[tid] = bx.x; s_y1[tid] = bx.y; s_x2[tid] = bx.z; s_y2[tid] = bx.w;
        s_kindi[tid] = myk_cls;
        s_area[tid] = fmaxf(bx.z - bx.x, 0.f) * fmaxf(bx.w - bx.y, 0.f);
    }
    __syncthreads();

    // ---- exclusive prefix over 80 (padded 96) class counts: warp 0 ----
    if (tid < 32) {
        int c0 = tid * 3;
        u32 a0 = s_ccnt[c0], a1 = s_ccnt[c0 + 1], a2 = s_ccnt[c0 + 2];
        u32 tot3 = a0 + a1 + a2;
        u32 x = tot3;
        #pragma unroll
        for (int off = 1; off < 32; off <<= 1) {
            u32 y = __shfl_up_sync(FULLM, x, off);
            if (lane >= off) x += y;
        }
        u32 excl = x - tot3;
        s_coff[c0]     = excl;           s_cwr[c0]     = excl;
        s_coff[c0 + 1] = excl + a0;      s_cwr[c0 + 1] = excl + a0;
        s_coff[c0 + 2] = excl + a0 + a1; s_cwr[c0 + 2] = excl + a0 + a1;
    }
    __syncthreads();

    // ---- scatter into class lists (match-dedup'd) ----
    int myrank = 0;
    if (tid < KTOP) {
        u32 act    = __activemask();
        u32 peers  = __match_any_sync(act, myk_cls);
        int leader = __ffs(peers) - 1;
        u32 prior  = (u32)__popc(peers & ((1u << lane) - 1u));
        u32 base   = 0;
        if (lane == leader) base = atomicAdd(&s_cwr[myk_cls], (u32)__popc(peers));
        base = __shfl_sync(act, base, leader);
        u32 slot = base + prior;
        myrank = (int)(slot - s_coff[myk_cls]);
        s_list[slot] = (u32)tid;
    }
    __syncthreads();

    // ---- same-class pair compare -> sparse mask bits + flags ----
    if (tid < KTOP) {
        int off = (int)s_coff[myk_cls];
        int n   = (int)s_cwr[myk_cls] - off;
        float bx1 = s_x1[tid], by1 = s_y1[tid], bx2 = s_x2[tid], by2 = s_y2[tid];
        for (int r = myrank + 1; r < n; r++) {
            int o = (int)s_list[off + r];
            float xx1 = fmaxf(bx1, s_x1[o]);
            float yy1 = fmaxf(by1, s_y1[o]);
            float xx2 = fminf(bx2, s_x2[o]);
            float yy2 = fminf(by2, s_y2[o]);
            float inter = fmaxf(xx2 - xx1, 0.f) * fmaxf(yy2 - yy1, 0.f);
            int i = min(tid, o), j = max(tid, o);
            float denom = s_area[i] + s_area[j] - inter + 1e-9f;
            if (inter > 0.5f * denom) {
                atomicOr(&s_mask[i * 32 + (j >> 5)], 1u << (j & 31));
                atomicOr(&s_rowany[i], 1u);
                if ((i >> 5) == (j >> 5)) atomicOr(&s_diagany[i >> 5], 1u);
            }
        }
    }
    __syncthreads();

    // ---- sparsity-aware serial sweep on warp 0 ----
    if (tid < 32) {
        u32 rem = 0;
        for (int c = 0; c < 32; c++) {
            u32 ra = s_rowany[c * 32 + lane];
            if (__reduce_or_sync(FULLM, ra) == 0u) continue;
            u32 cur = __shfl_sync(FULLM, rem, c);
            if (s_diagany[c] == 0u) {
                u32 K = ~cur;
                u32 a0 = 0, a1 = 0, a2 = 0, a3 = 0;
                #pragma unroll
                for (int k = 0; k < 32; k += 4) {
                    a0 |= s_mask[(c * 32 + k    ) * 32 + lane] & (u32)(((int)(K << (31 - k)))       >> 31);
                    a1 |= s_mask[(c * 32 + k + 1) * 32 + lane] & (u32)(((int)(K << (31 - (k + 1)))) >> 31);
                    a2 |= s_mask[(c * 32 + k + 2) * 32 + lane] & (u32)(((int)(K << (31 - (k + 2)))) >> 31);
                    a3 |= s_mask[(c * 32 + k + 3) * 32 + lane] & (u32)(((int)(K << (31 - (k + 3)))) >> 31);
                }
                rem |= (a0 | a1) | (a2 | a3);
            } else {
                u32 acc = 0;
                #pragma unroll 4
                for (int k = 0; k < 32; k++) {
                    if (!((cur >> k) & 1u)) {
                        acc |= s_mask[(c * 32 + k) * 32 + lane];
                        cur |= s_mask[(c * 32 + k) * 32 + c];
                    }
                }
                rem |= acc;
            }
        }
        s_remw[lane] = rem;
    }
    __syncthreads();

    // ---- output ----
    if (tid < KTOP) {
        bool removed = (s_remw[tid >> 5] >> (tid & 31)) & 1u;
        float sc = __uint_as_float(my_sc);
        float out_sc = (!removed && sc > 0.0f) ? sc : 0.0f;
        float* op = out + ((size_t)b * KTOP + tid) * 6;
        op[0] = s_x1[tid]; op[1] = s_y1[tid]; op[2] = s_x2[tid]; op[3] = s_y2[tid];
        op[4] = (float)s_kindi[tid];
        op[5] = out_sc;
    }
}

// ---------------------------------------------------------------------------
extern "C" void kernel_launch(void* const* d_in, const int* in_sizes, int n_in,
                              void* d_out, int out_size) {
    bool dict_order = (in_sizes[1] != 2621440);
    Ptrs p;
    for (int i = 0; i < 5; i++) {
        if (dict_order) {
            p.cls[i] = (const float*)d_in[3 * i];
            p.reg[i] = (const float*)d_in[3 * i + 2];
        } else {
            p.cls[i] = (const float*)d_in[i];
            p.reg[i] = (const float*)d_in[10 + i];
        }
    }

    int total = BATCH * NPOS;
    decode_kernel<<<(total + 255) / 256, 256>>>(p);

    cudaFuncSetAttribute(fused_kernel,
                         cudaFuncAttributeMaxDynamicSharedMemorySize, DYN_TOTAL);
    fused_kernel<<<BATCH, 1024, DYN_TOTAL>>>((float*)d_out);
}